// round 16
// baseline (speedup 1.0000x reference)
#include <cuda_runtime.h>
#include <cstdint>

// Lanczos upsample (4,2,256,256) f32 -> (4,2,2048,2048) f32, 8x per axis.
//
// Algebra (validated, rel_err ~1.4e-7): reference nearest-gather + 9-tap
// LUT-Lanczos collapses to a 2x2 weighted gather with 8 compile-time phase
// weight pairs per axis; reflect padding == clamp to boundary source pixel.
//
// Round 16: R10/R13 family (4-row span, 32KB smem, grid 4096 -- the proven
// best) with the commit SPLIT into two 16KB halves: first committed as soon
// as rows 0-1 are staged, so the engine drains while the SM computes rows
// 2-3. Disjoint halves -> no reuse waits; final read-wait covers only the
// residual. R14/R15 established: early drain start + many independent
// blocks wins; single big commits and persistent loops lose.

namespace lw {

constexpr double PI = 3.14159265358979323846;

constexpr double csin(double x) {
    double k = x / (2.0 * PI);
    long long n = (long long)(k >= 0.0 ? k + 0.5 : k - 0.5);
    double r = x - (double)n * (2.0 * PI);
    if (r > PI * 0.5)       r =  PI - r;
    else if (r < -PI * 0.5) r = -PI - r;
    double term = r, sum = r;
    const double r2 = r * r;
    for (int i = 1; i <= 11; ++i) {
        term *= -r2 / ((2.0 * i) * (2.0 * i + 1.0));
        sum += term;
    }
    return sum;
}

constexpr double tap(double d, int p) {
    double t  = d + (double)(p - 4);
    double tp = t * PI;
    double tq = tp * 0.25;
    return (csin(tp) / tp) * (csin(tq) / tq);
}

constexpr float wA(int f) {
    double d = 1e-8 + (double)f / 8.0;
    int r = (f + 4) & 7;
    double a = 0.0;
    for (int p = 0; p < 8 - r; ++p) a += tap(d, p);
    return (float)a;
}
constexpr float wB(int f) {
    double d = 1e-8 + (double)f / 8.0;
    int r = (f + 4) & 7;
    double b = 0.0;
    for (int p = 8 - r; p <= 8; ++p) b += tap(d, p);
    return (float)b;
}

} // namespace lw

// Scalar host constexprs fold into device code as literals (proven pattern).
constexpr float A0 = lw::wA(0), A1 = lw::wA(1), A2 = lw::wA(2), A3 = lw::wA(3);
constexpr float A4 = lw::wA(4), A5 = lw::wA(5), A6 = lw::wA(6), A7 = lw::wA(7);
constexpr float B0 = lw::wB(0), B1 = lw::wB(1), B2 = lw::wB(2), B3 = lw::wB(3);
constexpr float B4 = lw::wB(4), B5 = lw::wB(5), B6 = lw::wB(6), B7 = lw::wB(7);

template <int F> __device__ __forceinline__ constexpr float getA() {
    if constexpr (F == 0) return A0; else if constexpr (F == 1) return A1;
    else if constexpr (F == 2) return A2; else if constexpr (F == 3) return A3;
    else if constexpr (F == 4) return A4; else if constexpr (F == 5) return A5;
    else if constexpr (F == 6) return A6; else return A7;
}
template <int F> __device__ __forceinline__ constexpr float getB() {
    if constexpr (F == 0) return B0; else if constexpr (F == 1) return B1;
    else if constexpr (F == 2) return B2; else if constexpr (F == 3) return B3;
    else if constexpr (F == 4) return B4; else if constexpr (F == 5) return B5;
    else if constexpr (F == 6) return B6; else return B7;
}

__device__ __forceinline__ uint32_t smem_u32(const void* p) {
    uint32_t a;
    asm("{ .reg .u64 t; cvta.to.shared.u64 t, %1; cvt.u32.u64 %0, t; }"
        : "=r"(a) : "l"(p));
    return a;
}

// Compute row at y-phase FY (compile time) into smem. x-phases 0..3 use
// source cols (k-1,k); 4..7 use (k,k+1).
template <int FY>
__device__ __forceinline__ void compute_row(
    float* __restrict__ srow, int k,
    float s00, float s01, float s02, float s10, float s11, float s12)
{
    constexpr float Ay = getA<FY>();
    constexpr float By = getB<FY>();

    const float v0 = Ay * s00 + By * s10;
    const float v1 = Ay * s01 + By * s11;
    const float v2 = Ay * s02 + By * s12;

    float4 o0, o1;
    o0.x = A0 * v0 + B0 * v1;
    o0.y = A1 * v0 + B1 * v1;
    o0.z = A2 * v0 + B2 * v1;
    o0.w = A3 * v0 + B3 * v1;
    o1.x = A4 * v1 + B4 * v2;
    o1.y = A5 * v1 + B5 * v2;
    o1.z = A6 * v1 + B6 * v2;
    o1.w = A7 * v1 + B7 * v2;

    float4* sp = reinterpret_cast<float4*>(srow + k * 8);
    sp[0] = o0;
    sp[1] = o1;
}

__device__ __forceinline__ void bulk_commit16k(const float* sbuf, float* gdst) {
    // Caller guarantees a preceding __syncthreads; thread 0 only.
    asm volatile("fence.proxy.async.shared::cta;" ::: "memory");
    unsigned long long policy;
    asm volatile("createpolicy.fractional.L2::evict_first.b64 %0, 1.0;"
                 : "=l"(policy));
    asm volatile(
        "cp.async.bulk.global.shared::cta.bulk_group.L2::cache_hint"
        " [%0], [%1], %2, %3;"
        :: "l"((unsigned long long)gdst), "r"(smem_u32(sbuf)),
           "n"(16384), "l"(policy) : "memory");
    asm volatile("cp.async.bulk.commit_group;" ::: "memory");
}

// Grid: 8 channels x 512 four-row spans. Block (bc, m) produces output rows
// y = 4m..4m+3 (contiguous 32KB), all blending source rows ry0=clamp((4m-4)>>3)
// and ry1=ry0+1 clamped. Thread k owns output columns 8k..8k+7 from source
// columns k-1,k,k+1. Two 16KB half-commits; first issued after rows 0-1.
template <int P>   // P = 0: y-phases 0..3; P = 1: y-phases 4..7
__device__ __forceinline__ void emit_span(
    float* __restrict__ rowbuf, float* __restrict__ gdst, int k,
    float s00, float s01, float s02, float s10, float s11, float s12)
{
    constexpr int F = 4 * P;
    // Half 1: rows +0,+1 -> first 16KB, commit immediately.
    compute_row<F + 0>(rowbuf,        k, s00, s01, s02, s10, s11, s12);
    compute_row<F + 1>(rowbuf + 2048, k, s00, s01, s02, s10, s11, s12);
    __syncthreads();
    if (threadIdx.x == 0) bulk_commit16k(rowbuf, gdst);

    // Half 2: rows +2,+3 -> second (disjoint) 16KB, computed during drain.
    compute_row<F + 2>(rowbuf + 2 * 2048, k, s00, s01, s02, s10, s11, s12);
    compute_row<F + 3>(rowbuf + 3 * 2048, k, s00, s01, s02, s10, s11, s12);
    __syncthreads();
    if (threadIdx.x == 0) {
        bulk_commit16k(rowbuf + 2 * 2048, gdst + 2 * 2048);
        // Block must not exit until the engine has READ all smem.
        asm volatile("cp.async.bulk.wait_group.read 0;" ::: "memory");
    }
}

__global__ void __launch_bounds__(256)
lz_upsample_kernel(const float* __restrict__ img, float* __restrict__ out) {
    __shared__ __align__(128) float rowbuf[4][2048];   // 32 KB

    const int b  = blockIdx.x;
    const int bc = b >> 9;               // channel 0..7
    const int m  = b & 511;              // 4-row span index

    const int y0   = 4 * m;
    const int ry0u = (y0 - 4) >> 3;      // constant across the span
    const int ry0  = max(ry0u, 0);
    const int ry1  = min(ry0u + 1, 255);

    const float* __restrict__ base = img + (size_t)bc * 65536;
    const float* __restrict__ r0   = base + ry0 * 256;
    const float* __restrict__ r1   = base + ry1 * 256;

    const int k  = threadIdx.x;
    const int km = max(k - 1, 0);
    const int kp = min(k + 1, 255);

    const float s00 = __ldg(r0 + km), s01 = __ldg(r0 + k), s02 = __ldg(r0 + kp);
    const float s10 = __ldg(r1 + km), s11 = __ldg(r1 + k), s12 = __ldg(r1 + kp);

    float* const gdst = out + ((size_t)bc * 2048 + (size_t)y0) * 2048;

    if (m & 1)
        emit_span<1>(&rowbuf[0][0], gdst, k, s00, s01, s02, s10, s11, s12);
    else
        emit_span<0>(&rowbuf[0][0], gdst, k, s00, s01, s02, s10, s11, s12);
}

extern "C" void kernel_launch(void* const* d_in, const int* in_sizes, int n_in,
                              void* d_out, int out_size) {
    (void)in_sizes; (void)n_in; (void)out_size;
    const float* img = (const float*)d_in[0];
    float* out = (float*)d_out;

    lz_upsample_kernel<<<8 * 512, 256>>>(img, out);
}

// round 17
// speedup vs baseline: 1.0013x; 1.0013x over previous
#include <cuda_runtime.h>
#include <cstdint>

// Lanczos upsample (4,2,256,256) f32 -> (4,2,2048,2048) f32, 8x per axis.
//
// FINAL FORM (R13, benched 24.22/24.35us, rel_err 1.39e-7).
//
// Algebra: the reference's nearest-gather + 9-tap LUT-Lanczos on the
// upsampled grid collapses to a 2x2 weighted gather with 8 compile-time
// phase weight pairs per axis (phases exact: frac = (coord&7)/8); reflect
// padding == clamp to the boundary source pixel.
//
// Egress: one 32KB cp.async.bulk per block (4 contiguous output rows),
// L2 evict_first, grid 4096 (8 channels x 512 four-row spans).
//
// Optimization ledger: per-thread STG 34.8us -> bulk store 28.6 -> 4-row
// span 26.6 -> +evict_first 24.2 (floor). Falsified alternatives: row-group
// STG (43.0), pipelined drains (neutral), dual-engine STG+bulk (30.7),
// persistent single-wave (25.8), single 64KB commit (24.5), split 16KB
// early-commit (24.6), discard.global.L2 (CORRUPTS: weakly ordered vs bulk
// writes). The kernel sits at the steady-state write-stream ceiling:
// 134MB / ~22.4us ~ 6 TB/s L2 ingress, schedule-invariant.

namespace lw {

constexpr double PI = 3.14159265358979323846;

constexpr double csin(double x) {
    double k = x / (2.0 * PI);
    long long n = (long long)(k >= 0.0 ? k + 0.5 : k - 0.5);
    double r = x - (double)n * (2.0 * PI);
    if (r > PI * 0.5)       r =  PI - r;
    else if (r < -PI * 0.5) r = -PI - r;
    double term = r, sum = r;
    const double r2 = r * r;
    for (int i = 1; i <= 11; ++i) {
        term *= -r2 / ((2.0 * i) * (2.0 * i + 1.0));
        sum += term;
    }
    return sum;
}

constexpr double tap(double d, int p) {
    double t  = d + (double)(p - 4);
    double tp = t * PI;
    double tq = tp * 0.25;
    return (csin(tp) / tp) * (csin(tq) / tq);
}

constexpr float wA(int f) {
    double d = 1e-8 + (double)f / 8.0;
    int r = (f + 4) & 7;
    double a = 0.0;
    for (int p = 0; p < 8 - r; ++p) a += tap(d, p);
    return (float)a;
}
constexpr float wB(int f) {
    double d = 1e-8 + (double)f / 8.0;
    int r = (f + 4) & 7;
    double b = 0.0;
    for (int p = 8 - r; p <= 8; ++p) b += tap(d, p);
    return (float)b;
}

} // namespace lw

// Scalar host constexprs fold into device code as literals.
constexpr float A0 = lw::wA(0), A1 = lw::wA(1), A2 = lw::wA(2), A3 = lw::wA(3);
constexpr float A4 = lw::wA(4), A5 = lw::wA(5), A6 = lw::wA(6), A7 = lw::wA(7);
constexpr float B0 = lw::wB(0), B1 = lw::wB(1), B2 = lw::wB(2), B3 = lw::wB(3);
constexpr float B4 = lw::wB(4), B5 = lw::wB(5), B6 = lw::wB(6), B7 = lw::wB(7);

template <int F> __device__ __forceinline__ constexpr float getA() {
    if constexpr (F == 0) return A0; else if constexpr (F == 1) return A1;
    else if constexpr (F == 2) return A2; else if constexpr (F == 3) return A3;
    else if constexpr (F == 4) return A4; else if constexpr (F == 5) return A5;
    else if constexpr (F == 6) return A6; else return A7;
}
template <int F> __device__ __forceinline__ constexpr float getB() {
    if constexpr (F == 0) return B0; else if constexpr (F == 1) return B1;
    else if constexpr (F == 2) return B2; else if constexpr (F == 3) return B3;
    else if constexpr (F == 4) return B4; else if constexpr (F == 5) return B5;
    else if constexpr (F == 6) return B6; else return B7;
}

__device__ __forceinline__ uint32_t smem_u32(const void* p) {
    uint32_t a;
    asm("{ .reg .u64 t; cvta.to.shared.u64 t, %1; cvt.u32.u64 %0, t; }"
        : "=r"(a) : "l"(p));
    return a;
}

// Compute row at y-phase FY (compile time) into smem. x-phases 0..3 use
// source cols (k-1,k); 4..7 use (k,k+1).
template <int FY>
__device__ __forceinline__ void compute_row(
    float* __restrict__ srow, int k,
    float s00, float s01, float s02, float s10, float s11, float s12)
{
    constexpr float Ay = getA<FY>();
    constexpr float By = getB<FY>();

    const float v0 = Ay * s00 + By * s10;
    const float v1 = Ay * s01 + By * s11;
    const float v2 = Ay * s02 + By * s12;

    float4 o0, o1;
    o0.x = A0 * v0 + B0 * v1;
    o0.y = A1 * v0 + B1 * v1;
    o0.z = A2 * v0 + B2 * v1;
    o0.w = A3 * v0 + B3 * v1;
    o1.x = A4 * v1 + B4 * v2;
    o1.y = A5 * v1 + B5 * v2;
    o1.z = A6 * v1 + B6 * v2;
    o1.w = A7 * v1 + B7 * v2;

    float4* sp = reinterpret_cast<float4*>(srow + k * 8);
    sp[0] = o0;
    sp[1] = o1;
}

// Grid: 8 channels x 512 four-row spans. Block (bc, m) produces output rows
// y = 4m..4m+3 (contiguous 32KB), all blending source rows ry0=clamp((4m-4)>>3)
// and ry1=ry0+1 clamped. Thread k owns output columns 8k..8k+7 from source
// columns k-1,k,k+1.
__global__ void __launch_bounds__(256)
lz_upsample_kernel(const float* __restrict__ img, float* __restrict__ out) {
    __shared__ __align__(128) float rowbuf[4][2048];   // 32 KB

    const int b  = blockIdx.x;
    const int bc = b >> 9;               // channel 0..7
    const int m  = b & 511;              // 4-row span index

    const int y0   = 4 * m;
    const int ry0u = (y0 - 4) >> 3;      // constant across the span
    const int ry0  = max(ry0u, 0);
    const int ry1  = min(ry0u + 1, 255);

    const float* __restrict__ base = img + (size_t)bc * 65536;
    const float* __restrict__ r0   = base + ry0 * 256;
    const float* __restrict__ r1   = base + ry1 * 256;

    const int k  = threadIdx.x;
    const int km = max(k - 1, 0);
    const int kp = min(k + 1, 255);

    const float s00 = __ldg(r0 + km), s01 = __ldg(r0 + k), s02 = __ldg(r0 + kp);
    const float s10 = __ldg(r1 + km), s11 = __ldg(r1 + k), s12 = __ldg(r1 + kp);

    if (m & 1) {   // y-phases 4..7
        compute_row<4>(rowbuf[0], k, s00, s01, s02, s10, s11, s12);
        compute_row<5>(rowbuf[1], k, s00, s01, s02, s10, s11, s12);
        compute_row<6>(rowbuf[2], k, s00, s01, s02, s10, s11, s12);
        compute_row<7>(rowbuf[3], k, s00, s01, s02, s10, s11, s12);
    } else {       // y-phases 0..3
        compute_row<0>(rowbuf[0], k, s00, s01, s02, s10, s11, s12);
        compute_row<1>(rowbuf[1], k, s00, s01, s02, s10, s11, s12);
        compute_row<2>(rowbuf[2], k, s00, s01, s02, s10, s11, s12);
        compute_row<3>(rowbuf[3], k, s00, s01, s02, s10, s11, s12);
    }

    __syncthreads();

    if (threadIdx.x == 0) {
        // Order generic-proxy STS before the async-proxy bulk read.
        asm volatile("fence.proxy.async.shared::cta;" ::: "memory");
        const unsigned long long gdst =
            (unsigned long long)(out + ((size_t)bc * 2048 + (size_t)y0) * 2048);
        const uint32_t ssrc = smem_u32(rowbuf);
        // evict_first: output is never re-read; drain dirty lines eagerly so
        // steady-state replay doesn't burst-evict against the write wall.
        unsigned long long policy;
        asm volatile("createpolicy.fractional.L2::evict_first.b64 %0, 1.0;"
                     : "=l"(policy));
        asm volatile(
            "cp.async.bulk.global.shared::cta.bulk_group.L2::cache_hint"
            " [%0], [%1], %2, %3;"
            :: "l"(gdst), "r"(ssrc), "n"(32768), "l"(policy) : "memory");
        asm volatile("cp.async.bulk.commit_group;" ::: "memory");
        // Block must not exit until the engine has READ the smem buffer.
        asm volatile("cp.async.bulk.wait_group.read 0;" ::: "memory");
    }
}

extern "C" void kernel_launch(void* const* d_in, const int* in_sizes, int n_in,
                              void* d_out, int out_size) {
    (void)in_sizes; (void)n_in; (void)out_size;
    const float* img = (const float*)d_in[0];
    float* out = (float*)d_out;

    lz_upsample_kernel<<<8 * 512, 256>>>(img, out);
}